// round 7
// baseline (speedup 1.0000x reference)
#include <cuda_runtime.h>
#include <cub/cub.cuh>

#define BB 8
#define NN 2048
#define MM 2048
#define DIN 256
#define EE 128
#define LALPHA 0.01f
#define NCHUNK 32
#define CHUNK 64            // MM / NCHUNK

#define GEMM_BLOCKS 256
#define ATT1_BLOCKS 2048    // B*N / 8 rows-per-block

// ---------------- scratch (device globals; no allocation allowed) ----------------
__device__ float g_v1[DIN];
__device__ float g_att2[BB * MM];
__device__ float g_E1p[BB * NN], g_E1n[BB * NN], g_key[BB * NN];   // key = -att1
__device__ float g_F2p[BB * MM], g_F2n[BB * MM];
__device__ float g_Wh2[BB * MM * EE];
__device__ float g_sortv[BB * MM];
__device__ int   g_sortidx[BB * MM];
__device__ float g_chP[BB * NCHUNK * EE], g_chN[BB * NCHUNK * EE];
__device__ float g_chPs[BB * NCHUNK], g_chNs[BB * NCHUNK];
__device__ float g_offP[BB * NCHUNK * EE], g_offN[BB * NCHUNK * EE];
__device__ float g_offPs[BB * NCHUNK], g_offNs[BB * NCHUNK];
__device__ float g_sufP[BB * (MM + 1) * EE];   // suffix sums of F2p*Wh2 in sorted order
__device__ float g_preN[BB * (MM + 1) * EE];   // prefix sums of F2n*Wh2 in sorted order
__device__ float g_sufPs[BB * (MM + 1)], g_preNs[BB * (MM + 1)];

// ---------------- 1. v1 = W1 @ a1_top ----------------
__global__ void k_v(const float* __restrict__ W1, const float* __restrict__ a1) {
    int d = threadIdx.x;   // 0..255
    float s1 = 0.f;
    #pragma unroll 8
    for (int e = 0; e < EE; e++) s1 += W1[d * EE + e] * a1[e];
    g_v1[d] = s1;
}

// ---------------- 2. Wh2 GEMM (blocks 0..255) + att1 (blocks 256..2303) ----------------
__global__ void __launch_bounds__(256) k_wh2(const float* __restrict__ in2,
                                             const float* __restrict__ W1,
                                             const float* __restrict__ mask,
                                             const float* __restrict__ a1,
                                             const float* __restrict__ in1) {
    __shared__ float As[64 * 32];
    __shared__ float Bs[32 * 128];
    int tid = threadIdx.x;

    if (blockIdx.x >= GEMM_BLOCKS) {
        // ---- att1 path: 8 warps, one row each ----
        int w    = (blockIdx.x - GEMM_BLOCKS) * 8 + (tid >> 5);   // 0 .. B*N-1
        int lane = tid & 31;
        const float4* p  = (const float4*)(in1 + (size_t)w * DIN);
        const float4* v4 = (const float4*)g_v1;
        float acc = 0.f;
        #pragma unroll
        for (int i = 0; i < 2; i++) {
            float4 x  = p[lane + 32 * i];
            float4 vv = v4[lane + 32 * i];
            acc += x.x * vv.x + x.y * vv.y + x.z * vv.z + x.w * vv.w;
        }
        #pragma unroll
        for (int o = 16; o > 0; o >>= 1) acc += __shfl_xor_sync(0xffffffffu, acc, o);
        if (lane == 0) {
            g_E1p[w] = expf(acc);
            g_E1n[w] = expf(LALPHA * acc);
            g_key[w] = -acc;
        }
        return;
    }

    // ---- GEMM path ----
    int tx = tid & 31;    // column group -> cols tx*4..tx*4+3
    int ty = tid >> 5;    // row group   -> rows ty*8..ty*8+7 (one warp per ty)
    int row0 = blockIdx.x * 64;
    float acc[8][4];
    #pragma unroll
    for (int r = 0; r < 8; r++)
        #pragma unroll
        for (int c = 0; c < 4; c++) acc[r][c] = 0.f;

    for (int k0 = 0; k0 < DIN; k0 += 32) {
        #pragma unroll
        for (int i = tid; i < 512; i += 256) {
            int r = i >> 3, kq = i & 7;
            ((float4*)As)[i] = *(const float4*)(in2 + (size_t)(row0 + r) * DIN + k0 + kq * 4);
        }
        #pragma unroll
        for (int i = tid; i < 1024; i += 256) {
            ((float4*)Bs)[i] = ((const float4*)(W1 + (size_t)k0 * EE))[i];
        }
        __syncthreads();
        #pragma unroll
        for (int kk = 0; kk < 32; kk += 4) {
            float4 b0 = ((float4*)Bs)[(kk + 0) * 32 + tx];
            float4 b1 = ((float4*)Bs)[(kk + 1) * 32 + tx];
            float4 b2 = ((float4*)Bs)[(kk + 2) * 32 + tx];
            float4 b3 = ((float4*)Bs)[(kk + 3) * 32 + tx];
            #pragma unroll
            for (int r = 0; r < 8; r++) {
                float4 a4 = *(float4*)&As[(ty * 8 + r) * 32 + kk];   // warp-broadcast
                acc[r][0] += a4.x * b0.x + a4.y * b1.x + a4.z * b2.x + a4.w * b3.x;
                acc[r][1] += a4.x * b0.y + a4.y * b1.y + a4.z * b2.y + a4.w * b3.y;
                acc[r][2] += a4.x * b0.z + a4.y * b1.z + a4.z * b2.z + a4.w * b3.z;
                acc[r][3] += a4.x * b0.w + a4.y * b1.w + a4.z * b2.w + a4.w * b3.w;
            }
        }
        __syncthreads();
    }
    // epilogue: store Wh2 and compute att2 = Wh2 . a1[128:]
    float4 va = *(const float4*)(a1 + EE + tx * 4);
    #pragma unroll
    for (int r = 0; r < 8; r++) {
        int row = row0 + ty * 8 + r;
        *(float4*)(g_Wh2 + (size_t)row * EE + tx * 4) =
            make_float4(acc[r][0], acc[r][1], acc[r][2], acc[r][3]);
        float part = acc[r][0] * va.x + acc[r][1] * va.y + acc[r][2] * va.z + acc[r][3] * va.w;
        #pragma unroll
        for (int o = 16; o > 0; o >>= 1) part += __shfl_xor_sync(0xffffffffu, part, o);
        if (tx == 0) {
            int b = row >> 11, m = row & (MM - 1);
            float mk = mask[b * MM + m];
            g_att2[row] = part;
            g_F2p[row] = expf(part + mk);
            g_F2n[row] = expf(LALPHA * part + mk);
        }
    }
}

// ---------------- 3. per-batch radix sort of att2 (with index) ----------------
__global__ void __launch_bounds__(512) k_sort() {
    typedef cub::BlockRadixSort<float, 512, 4, int> Sorter;
    __shared__ typename Sorter::TempStorage tmp;
    int b = blockIdx.x;
    float key[4];
    int   val[4];
    #pragma unroll
    for (int i = 0; i < 4; i++) {
        int idx = threadIdx.x * 4 + i;
        key[i] = g_att2[b * MM + idx];
        val[i] = idx;
    }
    Sorter(tmp).Sort(key, val);
    #pragma unroll
    for (int i = 0; i < 4; i++) {
        int idx = threadIdx.x * 4 + i;
        g_sortv[b * MM + idx]   = key[i];
        g_sortidx[b * MM + idx] = val[i];
    }
}

// ---------------- staging helper: load one sorted chunk into smem ----------------
// sw[j][e] = Wh2[m_j, e]; sfp[j]=F2p[m_j]; sfn[j]=F2n[m_j]
__device__ __forceinline__ void stage_chunk(int b, int c, int e,
                                            float (*sw)[EE], float* sfp, float* sfn,
                                            int* sm) {
    int base = b * MM + c * CHUNK;
    if (e < CHUNK) sm[e] = g_sortidx[base + e];
    __syncthreads();
    #pragma unroll 8
    for (int j = 0; j < CHUNK; j++)
        sw[j][e] = g_Wh2[(size_t)(b * MM + sm[j]) * EE + e];
    if (e < CHUNK)  sfp[e] = g_F2p[b * MM + sm[e]];
    else if (e < 2 * CHUNK) sfn[e - CHUNK] = g_F2n[b * MM + sm[e - CHUNK]];
    __syncthreads();
}

// ---------------- 4a. chunk partial sums (sorted order, smem-staged) ----------------
__global__ void __launch_bounds__(EE) k_chunksum() {
    __shared__ float sw[CHUNK][EE];
    __shared__ float sfp[CHUNK], sfn[CHUNK];
    __shared__ int   sm[CHUNK];
    int b = blockIdx.y, c = blockIdx.x, e = threadIdx.x;
    stage_chunk(b, c, e, sw, sfp, sfn, sm);
    double aP = 0.0, aN = 0.0;
    #pragma unroll 8
    for (int j = 0; j < CHUNK; j++) {
        float w = sw[j][e];
        aP += (double)sfp[j] * w;
        aN += (double)sfn[j] * w;
    }
    g_chP[(b * NCHUNK + c) * EE + e] = (float)aP;
    g_chN[(b * NCHUNK + c) * EE + e] = (float)aN;
    if (e == 0) {
        double sP = 0.0, sN = 0.0;
        #pragma unroll 8
        for (int j = 0; j < CHUNK; j++) { sP += sfp[j]; sN += sfn[j]; }
        g_chPs[b * NCHUNK + c] = (float)sP;
        g_chNs[b * NCHUNK + c] = (float)sN;
    }
}

// ---------------- 4b. chunk-level offsets (forward for N, reverse for P) ----------------
__global__ void k_offsets() {
    int b = blockIdx.x, e = threadIdx.x;
    double run = 0.0;
    for (int c = 0; c < NCHUNK; c++) {
        g_offN[(b * NCHUNK + c) * EE + e] = (float)run;
        run += g_chN[(b * NCHUNK + c) * EE + e];
    }
    g_preN[((size_t)b * (MM + 1) + MM) * EE + e] = (float)run;
    double runP = 0.0;
    for (int c = NCHUNK - 1; c >= 0; c--) {
        g_offP[(b * NCHUNK + c) * EE + e] = (float)runP;
        runP += g_chP[(b * NCHUNK + c) * EE + e];
    }
    g_sufP[((size_t)b * (MM + 1) + MM) * EE + e] = 0.f;
    if (e == 0) {
        double r = 0.0;
        for (int c = 0; c < NCHUNK; c++) { g_offNs[b * NCHUNK + c] = (float)r; r += g_chNs[b * NCHUNK + c]; }
        g_preNs[b * (MM + 1) + MM] = (float)r;
        double rp = 0.0;
        for (int c = NCHUNK - 1; c >= 0; c--) { g_offPs[b * NCHUNK + c] = (float)rp; rp += g_chPs[b * NCHUNK + c]; }
        g_sufPs[b * (MM + 1) + MM] = 0.f;
    }
}

// ---------------- 4c. fine-grained prefix (N) and suffix (P) sums (smem-staged) ------
__global__ void __launch_bounds__(EE) k_scan() {
    __shared__ float sw[CHUNK][EE];
    __shared__ float sfp[CHUNK], sfn[CHUNK];
    __shared__ int   sm[CHUNK];
    int b = blockIdx.y, c = blockIdx.x, e = threadIdx.x;
    stage_chunk(b, c, e, sw, sfp, sfn, sm);

    // forward pass: prefix of F2n * Wh2
    {
        double runN  = (double)g_offN[(b * NCHUNK + c) * EE + e];
        double runNs = (e == 0) ? (double)g_offNs[b * NCHUNK + c] : 0.0;
        #pragma unroll 4
        for (int j = 0; j < CHUNK; j++) {
            int k = c * CHUNK + j;
            g_preN[((size_t)b * (MM + 1) + k) * EE + e] = (float)runN;
            if (e == 0) g_preNs[b * (MM + 1) + k] = (float)runNs;
            runN += (double)sfn[j] * sw[j][e];
            if (e == 0) runNs += sfn[j];
        }
    }
    // backward pass: suffix of F2p * Wh2
    {
        double runP  = (double)g_offP[(b * NCHUNK + c) * EE + e];
        double runPs = (e == 0) ? (double)g_offPs[b * NCHUNK + c] : 0.0;
        #pragma unroll 4
        for (int j = CHUNK - 1; j >= 0; j--) {
            int k = c * CHUNK + j;
            runP += (double)sfp[j] * sw[j][e];
            if (e == 0) runPs += sfp[j];
            g_sufP[((size_t)b * (MM + 1) + k) * EE + e] = (float)runP;
            if (e == 0) g_sufPs[b * (MM + 1) + k] = (float)runPs;
        }
    }
}

// ---------------- 5. fused rank + context + probs (8 rows per block) ----------------
__global__ void __launch_bounds__(512) k_rankprobs(float* __restrict__ out_ctx,
                                                   float* __restrict__ out_p) {
    __shared__ int   sk[8];
    __shared__ float sc1[8], sc2[8], skey[8];
    int g = blockIdx.x;            // 0 .. B*N/8 - 1
    int row0 = g * 8;
    int b = row0 >> 11;
    int tid = threadIdx.x;
    if (tid < 8) {
        int row = row0 + tid;
        float key = g_key[row];
        const float* sv = g_sortv + b * MM;
        int lo = 0, hi = MM;       // first index with sv[idx] > key
        while (lo < hi) {
            int mid = (lo + hi) >> 1;
            if (sv[mid] > key) hi = mid; else lo = mid + 1;
        }
        float E1p = g_E1p[row], E1n = g_E1n[row];
        float S = E1p * g_sufPs[b * (MM + 1) + lo] + E1n * g_preNs[b * (MM + 1) + lo];
        float invS = 1.f / S;
        sk[tid] = lo;
        sc1[tid] = E1p * invS;
        sc2[tid] = E1n * invS;
        skey[tid] = key;
    }
    __syncthreads();
    // context: 4 rows per pass, 2 passes
    {
        int e = tid & (EE - 1);
        int rb = tid >> 7;         // 0..3
        #pragma unroll
        for (int it = 0; it < 2; it++) {
            int r = it * 4 + rb;
            int row = row0 + r;
            int k = sk[r];
            float num = sc1[r] * g_sufP[((size_t)b * (MM + 1) + k) * EE + e]
                      + sc2[r] * g_preN[((size_t)b * (MM + 1) + k) * EE + e];
            out_ctx[(size_t)row * EE + e] = num;
        }
    }
    // probs: per-batch vectors held in registers, 8 output rows
    const float4 tv = ((const float4*)(g_att2 + b * MM))[tid];
    const float4 pv = ((const float4*)(g_F2p + b * MM))[tid];
    const float4 nv = ((const float4*)(g_F2n + b * MM))[tid];
    #pragma unroll
    for (int r = 0; r < 8; r++) {
        int row = row0 + r;
        float key = skey[r], c1 = sc1[r], c2 = sc2[r];
        float4 o;
        o.x = (tv.x > key) ? c1 * pv.x : c2 * nv.x;
        o.y = (tv.y > key) ? c1 * pv.y : c2 * nv.y;
        o.z = (tv.z > key) ? c1 * pv.z : c2 * nv.z;
        o.w = (tv.w > key) ? c1 * pv.w : c2 * nv.w;
        ((float4*)(out_p + (size_t)row * MM))[tid] = o;
    }
}

// ---------------- launch ----------------
extern "C" void kernel_launch(void* const* d_in, const int* in_sizes, int n_in,
                              void* d_out, int out_size) {
    const float* in1  = (const float*)d_in[0];   // (8,2048,256)
    const float* in2  = (const float*)d_in[1];   // (8,2048,256)
    const float* mask = (const float*)d_in[2];   // (8,1,2048)
    const float* W1   = (const float*)d_in[3];   // (256,128)
    const float* a1   = (const float*)d_in[4];   // (256,1)
    float* out = (float*)d_out;
    float* out_ctx   = out;                              // (8,2048,128)
    float* out_probs = out + (size_t)BB * NN * EE;       // (8,2048,2048)

    k_v<<<1, 256>>>(W1, a1);
    k_wh2<<<GEMM_BLOCKS + ATT1_BLOCKS, 256>>>(in2, W1, mask, a1, in1);
    k_sort<<<BB, 512>>>();
    dim3 gc(NCHUNK, BB);
    k_chunksum<<<gc, EE>>>();
    k_offsets<<<BB, EE>>>();
    k_scan<<<gc, EE>>>();
    k_rankprobs<<<BB * NN / 8, 512>>>(out_ctx, out_probs);
}

// round 8
// speedup vs baseline: 1.4683x; 1.4683x over previous
#include <cuda_runtime.h>
#include <cub/cub.cuh>

#define BB 8
#define NN 2048
#define MM 2048
#define DIN 256
#define EE 128
#define LALPHA 0.01f
#define NCHUNK 32
#define CHUNK 64            // MM / NCHUNK

#define GEMM_BLOCKS 256
#define ATT1_BLOCKS 2048    // B*N / 8 rows-per-block

// ---------------- scratch (device globals; no allocation allowed) ----------------
__device__ float g_v1[DIN];
__device__ float g_att2[BB * MM];
__device__ float g_E1p[BB * NN], g_E1n[BB * NN], g_key[BB * NN];   // key = -att1
__device__ float g_F2p[BB * MM], g_F2n[BB * MM];
__device__ float g_Wh2[BB * MM * EE];
__device__ float g_sortv[BB * MM];
__device__ int   g_sortidx[BB * MM];
__device__ float g_chP[BB * NCHUNK * EE], g_chN[BB * NCHUNK * EE];
__device__ float g_chPs[BB * NCHUNK], g_chNs[BB * NCHUNK];
__device__ float g_offP[BB * NCHUNK * EE], g_offN[BB * NCHUNK * EE];
__device__ float g_offPs[BB * NCHUNK], g_offNs[BB * NCHUNK];
__device__ float g_sufP[BB * (MM + 1) * EE];   // suffix sums of F2p*Wh2 in sorted order
__device__ float g_preN[BB * (MM + 1) * EE];   // prefix sums of F2n*Wh2 in sorted order
__device__ float g_sufPs[BB * (MM + 1)], g_preNs[BB * (MM + 1)];

// ---------------- 1. v1 = W1 @ a1_top ----------------
__global__ void k_v(const float* __restrict__ W1, const float* __restrict__ a1) {
    int d = threadIdx.x;   // 0..255
    float s1 = 0.f;
    #pragma unroll 8
    for (int e = 0; e < EE; e++) s1 += W1[d * EE + e] * a1[e];
    g_v1[d] = s1;
}

// ---------------- 2. Wh2 GEMM (blocks 0..255) + att1 (blocks 256..2303) ----------------
__global__ void __launch_bounds__(256) k_wh2(const float* __restrict__ in2,
                                             const float* __restrict__ W1,
                                             const float* __restrict__ mask,
                                             const float* __restrict__ a1,
                                             const float* __restrict__ in1) {
    __shared__ float As[64 * 32];
    __shared__ float Bs[32 * 128];
    int tid = threadIdx.x;

    if (blockIdx.x >= GEMM_BLOCKS) {
        // ---- att1 path: 8 warps, one row each ----
        int w    = (blockIdx.x - GEMM_BLOCKS) * 8 + (tid >> 5);   // 0 .. B*N-1
        int lane = tid & 31;
        const float4* p  = (const float4*)(in1 + (size_t)w * DIN);
        const float4* v4 = (const float4*)g_v1;
        float acc = 0.f;
        #pragma unroll
        for (int i = 0; i < 2; i++) {
            float4 x  = p[lane + 32 * i];
            float4 vv = v4[lane + 32 * i];
            acc += x.x * vv.x + x.y * vv.y + x.z * vv.z + x.w * vv.w;
        }
        #pragma unroll
        for (int o = 16; o > 0; o >>= 1) acc += __shfl_xor_sync(0xffffffffu, acc, o);
        if (lane == 0) {
            g_E1p[w] = expf(acc);
            g_E1n[w] = expf(LALPHA * acc);
            g_key[w] = -acc;
        }
        return;
    }

    // ---- GEMM path ----
    int tx = tid & 31;    // column group -> cols tx*4..tx*4+3
    int ty = tid >> 5;    // row group   -> rows ty*8..ty*8+7 (one warp per ty)
    int row0 = blockIdx.x * 64;
    float acc[8][4];
    #pragma unroll
    for (int r = 0; r < 8; r++)
        #pragma unroll
        for (int c = 0; c < 4; c++) acc[r][c] = 0.f;

    for (int k0 = 0; k0 < DIN; k0 += 32) {
        #pragma unroll
        for (int i = tid; i < 512; i += 256) {
            int r = i >> 3, kq = i & 7;
            ((float4*)As)[i] = *(const float4*)(in2 + (size_t)(row0 + r) * DIN + k0 + kq * 4);
        }
        #pragma unroll
        for (int i = tid; i < 1024; i += 256) {
            ((float4*)Bs)[i] = ((const float4*)(W1 + (size_t)k0 * EE))[i];
        }
        __syncthreads();
        #pragma unroll
        for (int kk = 0; kk < 32; kk += 4) {
            float4 b0 = ((float4*)Bs)[(kk + 0) * 32 + tx];
            float4 b1 = ((float4*)Bs)[(kk + 1) * 32 + tx];
            float4 b2 = ((float4*)Bs)[(kk + 2) * 32 + tx];
            float4 b3 = ((float4*)Bs)[(kk + 3) * 32 + tx];
            #pragma unroll
            for (int r = 0; r < 8; r++) {
                float4 a4 = *(float4*)&As[(ty * 8 + r) * 32 + kk];   // warp-broadcast
                acc[r][0] += a4.x * b0.x + a4.y * b1.x + a4.z * b2.x + a4.w * b3.x;
                acc[r][1] += a4.x * b0.y + a4.y * b1.y + a4.z * b2.y + a4.w * b3.y;
                acc[r][2] += a4.x * b0.z + a4.y * b1.z + a4.z * b2.z + a4.w * b3.z;
                acc[r][3] += a4.x * b0.w + a4.y * b1.w + a4.z * b2.w + a4.w * b3.w;
            }
        }
        __syncthreads();
    }
    // epilogue: store Wh2 and compute att2 = Wh2 . a1[128:]
    float4 va = *(const float4*)(a1 + EE + tx * 4);
    #pragma unroll
    for (int r = 0; r < 8; r++) {
        int row = row0 + ty * 8 + r;
        *(float4*)(g_Wh2 + (size_t)row * EE + tx * 4) =
            make_float4(acc[r][0], acc[r][1], acc[r][2], acc[r][3]);
        float part = acc[r][0] * va.x + acc[r][1] * va.y + acc[r][2] * va.z + acc[r][3] * va.w;
        #pragma unroll
        for (int o = 16; o > 0; o >>= 1) part += __shfl_xor_sync(0xffffffffu, part, o);
        if (tx == 0) {
            int b = row >> 11, m = row & (MM - 1);
            float mk = mask[b * MM + m];
            g_att2[row] = part;
            g_F2p[row] = expf(part + mk);
            g_F2n[row] = expf(LALPHA * part + mk);
        }
    }
}

// ---------------- 3. per-batch radix sort of att2 (with index) ----------------
__global__ void __launch_bounds__(512) k_sort() {
    typedef cub::BlockRadixSort<float, 512, 4, int> Sorter;
    __shared__ typename Sorter::TempStorage tmp;
    int b = blockIdx.x;
    float key[4];
    int   val[4];
    #pragma unroll
    for (int i = 0; i < 4; i++) {
        int idx = threadIdx.x * 4 + i;
        key[i] = g_att2[b * MM + idx];
        val[i] = idx;
    }
    Sorter(tmp).Sort(key, val);
    #pragma unroll
    for (int i = 0; i < 4; i++) {
        int idx = threadIdx.x * 4 + i;
        g_sortv[b * MM + idx]   = key[i];
        g_sortidx[b * MM + idx] = val[i];
    }
}

// ---------------- staging helper: load one sorted chunk into smem ----------------
// sw[j][e] = Wh2[m_j, e]; sfp[j]=F2p[m_j]; sfn[j]=F2n[m_j]
__device__ __forceinline__ void stage_chunk(int b, int c, int e,
                                            float (*sw)[EE], float* sfp, float* sfn,
                                            int* sm) {
    int base = b * MM + c * CHUNK;
    if (e < CHUNK) sm[e] = g_sortidx[base + e];
    __syncthreads();
    #pragma unroll 8
    for (int j = 0; j < CHUNK; j++)
        sw[j][e] = g_Wh2[(size_t)(b * MM + sm[j]) * EE + e];
    if (e < CHUNK)  sfp[e] = g_F2p[b * MM + sm[e]];
    else if (e < 2 * CHUNK) sfn[e - CHUNK] = g_F2n[b * MM + sm[e - CHUNK]];
    __syncthreads();
}

// ---------------- 4a. chunk partial sums (sorted order, fp32, smem-staged) ----------
__global__ void __launch_bounds__(EE) k_chunksum() {
    __shared__ float sw[CHUNK][EE];
    __shared__ float sfp[CHUNK], sfn[CHUNK];
    __shared__ int   sm[CHUNK];
    int b = blockIdx.y, c = blockIdx.x, e = threadIdx.x;
    stage_chunk(b, c, e, sw, sfp, sfn, sm);
    // 4 interleaved partial chains per direction to break the dependency chain
    float aP0 = 0.f, aP1 = 0.f, aP2 = 0.f, aP3 = 0.f;
    float aN0 = 0.f, aN1 = 0.f, aN2 = 0.f, aN3 = 0.f;
    #pragma unroll
    for (int j = 0; j < CHUNK; j += 4) {
        aP0 += sfp[j + 0] * sw[j + 0][e];  aN0 += sfn[j + 0] * sw[j + 0][e];
        aP1 += sfp[j + 1] * sw[j + 1][e];  aN1 += sfn[j + 1] * sw[j + 1][e];
        aP2 += sfp[j + 2] * sw[j + 2][e];  aN2 += sfn[j + 2] * sw[j + 2][e];
        aP3 += sfp[j + 3] * sw[j + 3][e];  aN3 += sfn[j + 3] * sw[j + 3][e];
    }
    g_chP[(b * NCHUNK + c) * EE + e] = (aP0 + aP1) + (aP2 + aP3);
    g_chN[(b * NCHUNK + c) * EE + e] = (aN0 + aN1) + (aN2 + aN3);
    if (e == 0) {
        float sP = 0.f, sN = 0.f;
        #pragma unroll
        for (int j = 0; j < CHUNK; j++) { sP += sfp[j]; sN += sfn[j]; }
        g_chPs[b * NCHUNK + c] = sP;
        g_chNs[b * NCHUNK + c] = sN;
    }
}

// ---------------- 4b. chunk-level offsets (fp64 anchor; tiny kernel) ----------------
__global__ void k_offsets() {
    int b = blockIdx.x, e = threadIdx.x;
    double run = 0.0;
    for (int c = 0; c < NCHUNK; c++) {
        g_offN[(b * NCHUNK + c) * EE + e] = (float)run;
        run += (double)g_chN[(b * NCHUNK + c) * EE + e];
    }
    g_preN[((size_t)b * (MM + 1) + MM) * EE + e] = (float)run;
    double runP = 0.0;
    for (int c = NCHUNK - 1; c >= 0; c--) {
        g_offP[(b * NCHUNK + c) * EE + e] = (float)runP;
        runP += (double)g_chP[(b * NCHUNK + c) * EE + e];
    }
    g_sufP[((size_t)b * (MM + 1) + MM) * EE + e] = 0.f;
    if (e == 0) {
        double r = 0.0;
        for (int c = 0; c < NCHUNK; c++) { g_offNs[b * NCHUNK + c] = (float)r; r += (double)g_chNs[b * NCHUNK + c]; }
        g_preNs[b * (MM + 1) + MM] = (float)r;
        double rp = 0.0;
        for (int c = NCHUNK - 1; c >= 0; c--) { g_offPs[b * NCHUNK + c] = (float)rp; rp += (double)g_chPs[b * NCHUNK + c]; }
        g_sufPs[b * (MM + 1) + MM] = 0.f;
    }
}

// ---------------- 4c. fine-grained prefix (N) and suffix (P) sums (fp32) ------------
__global__ void __launch_bounds__(EE) k_scan() {
    __shared__ float sw[CHUNK][EE];
    __shared__ float sfp[CHUNK], sfn[CHUNK];
    __shared__ int   sm[CHUNK];
    int b = blockIdx.y, c = blockIdx.x, e = threadIdx.x;
    stage_chunk(b, c, e, sw, sfp, sfn, sm);

    // forward pass: prefix of F2n * Wh2
    {
        float runN  = g_offN[(b * NCHUNK + c) * EE + e];
        float runNs = (e == 0) ? g_offNs[b * NCHUNK + c] : 0.f;
        #pragma unroll 8
        for (int j = 0; j < CHUNK; j++) {
            int k = c * CHUNK + j;
            g_preN[((size_t)b * (MM + 1) + k) * EE + e] = runN;
            if (e == 0) g_preNs[b * (MM + 1) + k] = runNs;
            runN += sfn[j] * sw[j][e];
            if (e == 0) runNs += sfn[j];
        }
    }
    // backward pass: suffix of F2p * Wh2
    {
        float runP  = g_offP[(b * NCHUNK + c) * EE + e];
        float runPs = (e == 0) ? g_offPs[b * NCHUNK + c] : 0.f;
        #pragma unroll 8
        for (int j = CHUNK - 1; j >= 0; j--) {
            int k = c * CHUNK + j;
            runP += sfp[j] * sw[j][e];
            if (e == 0) runPs += sfp[j];
            g_sufP[((size_t)b * (MM + 1) + k) * EE + e] = runP;
            if (e == 0) g_sufPs[b * (MM + 1) + k] = runPs;
        }
    }
}

// ---------------- 5. fused rank + context + probs (8 rows per block) ----------------
__global__ void __launch_bounds__(512) k_rankprobs(float* __restrict__ out_ctx,
                                                   float* __restrict__ out_p) {
    __shared__ int   sk[8];
    __shared__ float sc1[8], sc2[8], skey[8];
    int g = blockIdx.x;            // 0 .. B*N/8 - 1
    int row0 = g * 8;
    int b = row0 >> 11;
    int tid = threadIdx.x;
    if (tid < 8) {
        int row = row0 + tid;
        float key = g_key[row];
        const float* sv = g_sortv + b * MM;
        int lo = 0, hi = MM;       // first index with sv[idx] > key
        while (lo < hi) {
            int mid = (lo + hi) >> 1;
            if (sv[mid] > key) hi = mid; else lo = mid + 1;
        }
        float E1p = g_E1p[row], E1n = g_E1n[row];
        float S = E1p * g_sufPs[b * (MM + 1) + lo] + E1n * g_preNs[b * (MM + 1) + lo];
        float invS = 1.f / S;
        sk[tid] = lo;
        sc1[tid] = E1p * invS;
        sc2[tid] = E1n * invS;
        skey[tid] = key;
    }
    __syncthreads();
    // context: 4 rows per pass, 2 passes
    {
        int e = tid & (EE - 1);
        int rb = tid >> 7;         // 0..3
        #pragma unroll
        for (int it = 0; it < 2; it++) {
            int r = it * 4 + rb;
            int row = row0 + r;
            int k = sk[r];
            float num = sc1[r] * g_sufP[((size_t)b * (MM + 1) + k) * EE + e]
                      + sc2[r] * g_preN[((size_t)b * (MM + 1) + k) * EE + e];
            out_ctx[(size_t)row * EE + e] = num;
        }
    }
    // probs: per-batch vectors held in registers, 8 output rows
    const float4 tv = ((const float4*)(g_att2 + b * MM))[tid];
    const float4 pv = ((const float4*)(g_F2p + b * MM))[tid];
    const float4 nv = ((const float4*)(g_F2n + b * MM))[tid];
    #pragma unroll
    for (int r = 0; r < 8; r++) {
        int row = row0 + r;
        float key = skey[r], c1 = sc1[r], c2 = sc2[r];
        float4 o;
        o.x = (tv.x > key) ? c1 * pv.x : c2 * nv.x;
        o.y = (tv.y > key) ? c1 * pv.y : c2 * nv.y;
        o.z = (tv.z > key) ? c1 * pv.z : c2 * nv.z;
        o.w = (tv.w > key) ? c1 * pv.w : c2 * nv.w;
        ((float4*)(out_p + (size_t)row * MM))[tid] = o;
    }
}

// ---------------- launch ----------------
extern "C" void kernel_launch(void* const* d_in, const int* in_sizes, int n_in,
                              void* d_out, int out_size) {
    const float* in1  = (const float*)d_in[0];   // (8,2048,256)
    const float* in2  = (const float*)d_in[1];   // (8,2048,256)
    const float* mask = (const float*)d_in[2];   // (8,1,2048)
    const float* W1   = (const float*)d_in[3];   // (256,128)
    const float* a1   = (const float*)d_in[4];   // (256,1)
    float* out = (float*)d_out;
    float* out_ctx   = out;                              // (8,2048,128)
    float* out_probs = out + (size_t)BB * NN * EE;       // (8,2048,2048)

    k_v<<<1, 256>>>(W1, a1);
    k_wh2<<<GEMM_BLOCKS + ATT1_BLOCKS, 256>>>(in2, W1, mask, a1, in1);
    k_sort<<<BB, 512>>>();
    dim3 gc(NCHUNK, BB);
    k_chunksum<<<gc, EE>>>();
    k_offsets<<<BB, EE>>>();
    k_scan<<<gc, EE>>>();
    k_rankprobs<<<BB * NN / 8, 512>>>(out_ctx, out_probs);
}